// round 5
// baseline (speedup 1.0000x reference)
#include <cuda_runtime.h>
#include <math.h>

#define NN 100000
#define NE 1600000
#define FIN 128
#define HD 64
#define NC 40

// ---------------- scratch (static device memory: allowed) ----------------
__device__ float g_h [NN * HD];
__device__ float g_h2[NN * HD];
__device__ float g_rn [NN];
__device__ float g_rn2[NN];
__device__ int   g_deg[NN];
__device__ int   g_cursor[NN];
__device__ int   g_rowptr[NN + 1];
__device__ int   g_csr[NE];

// ---------------- CSR build ----------------
__global__ void clear_deg_kernel() {
    int i = blockIdx.x * blockDim.x + threadIdx.x;
    if (i < NN) g_deg[i] = 0;
}

__global__ void hist_kernel(const int* __restrict__ dst) {
    int e = blockIdx.x * blockDim.x + threadIdx.x;
    if (e < NE) atomicAdd(&g_deg[dst[e]], 1);
}

// single-block exclusive scan of g_deg -> g_rowptr (+copy to g_cursor)
__global__ void scan_kernel() {
    __shared__ int wsum[32];
    const int lane = threadIdx.x & 31;
    const int wid  = threadIdx.x >> 5;
    int carry = 0;
    for (int base = 0; base < NN; base += 1024) {
        int i = base + threadIdx.x;
        int v = (i < NN) ? g_deg[i] : 0;
        int incl = v;
        #pragma unroll
        for (int off = 1; off < 32; off <<= 1) {
            int t = __shfl_up_sync(0xffffffffu, incl, off);
            if (lane >= off) incl += t;
        }
        if (lane == 31) wsum[wid] = incl;
        __syncthreads();
        if (wid == 0) {
            int s = wsum[lane];
            #pragma unroll
            for (int off = 1; off < 32; off <<= 1) {
                int t = __shfl_up_sync(0xffffffffu, s, off);
                if (lane >= off) s += t;
            }
            wsum[lane] = s;
        }
        __syncthreads();
        int woff = (wid > 0) ? wsum[wid - 1] : 0;
        int excl = carry + woff + incl - v;
        if (i < NN) { g_rowptr[i] = excl; g_cursor[i] = excl; }
        carry += wsum[31];
        __syncthreads();
    }
    if (threadIdx.x == 0) g_rowptr[NN] = carry;
}

__global__ void scatter_kernel(const int* __restrict__ src, const int* __restrict__ dst) {
    int e = blockIdx.x * blockDim.x + threadIdx.x;
    if (e < NE) {
        int d = dst[e];
        int pos = atomicAdd(&g_cursor[d], 1);
        g_csr[pos] = src[e];
    }
}

// ---------------- GEMM1: h = relu(x @ W1 + b1), plus inv-norms ----------------
// block = 256 threads, 32 rows/block. thread (r = tid>>3, cg = tid&7) computes
// row r, cols cg*8..cg*8+7. W1 staged fully in smem; x staged in 2 half-K phases.
__global__ __launch_bounds__(256) void gemm1_kernel(const float* __restrict__ x,
                                                    const float* __restrict__ W1,
                                                    const float* __restrict__ b1) {
    __shared__ __align__(16) float Ws[FIN * HD];   // 32 KB
    __shared__ float xs[32 * 65];                  // padded, 8.3 KB
    __shared__ float bs[HD];

    const int tid = threadIdx.x;
    for (int i = tid; i < FIN * HD; i += 256) Ws[i] = W1[i];
    if (tid < HD) bs[tid] = b1[tid];

    const int row0 = blockIdx.x * 32;
    const int r  = tid >> 3;
    const int cg = tid & 7;

    float acc[8];
    #pragma unroll
    for (int i = 0; i < 8; i++) acc[i] = 0.f;

    for (int ph = 0; ph < 2; ph++) {
        __syncthreads();
        for (int i = tid; i < 32 * 64; i += 256) {
            int rr = i >> 6, cc = i & 63;
            xs[rr * 65 + cc] = x[(row0 + rr) * FIN + ph * 64 + cc];
        }
        __syncthreads();
        #pragma unroll 8
        for (int k = 0; k < 64; k++) {
            float xv = xs[r * 65 + k];
            const float4* wp = (const float4*)&Ws[(ph * 64 + k) * HD + cg * 8];
            float4 w0 = wp[0], w1 = wp[1];
            acc[0] = fmaf(xv, w0.x, acc[0]);
            acc[1] = fmaf(xv, w0.y, acc[1]);
            acc[2] = fmaf(xv, w0.z, acc[2]);
            acc[3] = fmaf(xv, w0.w, acc[3]);
            acc[4] = fmaf(xv, w1.x, acc[4]);
            acc[5] = fmaf(xv, w1.y, acc[5]);
            acc[6] = fmaf(xv, w1.z, acc[6]);
            acc[7] = fmaf(xv, w1.w, acc[7]);
        }
    }

    float nrm = 0.f;
    #pragma unroll
    for (int i = 0; i < 8; i++) {
        float v = acc[i] + bs[cg * 8 + i];
        v = fmaxf(v, 0.f);
        acc[i] = v;
        nrm = fmaf(v, v, nrm);
    }
    // reduce across the 8 threads of the same row (consecutive lanes)
    #pragma unroll
    for (int off = 1; off < 8; off <<= 1) nrm += __shfl_xor_sync(0xffffffffu, nrm, off);

    const int row = row0 + r;
    float4* out = (float4*)&g_h[row * HD + cg * 8];
    out[0] = make_float4(acc[0], acc[1], acc[2], acc[3]);
    out[1] = make_float4(acc[4], acc[5], acc[6], acc[7]);
    if (cg == 0) g_rn[row] = 1.0f / fmaxf(sqrtf(nrm), 1e-12f);
}

// ---------------- AGNN layer: warp per node, fused gather+softmax ----------------
// out_i = sum_j exp(cos(h_i,h_j)) * h_j / sum_j exp(cos(h_i,h_j))   (j: in-edges + self)
// cos(h_i,h_j) = rn_i * rn_j * dot(h_i, h_j); softmax shift-invariance lets us drop
// the segment max (|logit| <= 1). Also emits inv-norm of the new row for next layer.
__global__ __launch_bounds__(256) void agnn_kernel(const float* __restrict__ hin,
                                                   float* __restrict__ hout,
                                                   const float* __restrict__ rn_in,
                                                   float* __restrict__ rn_out) {
    const int node = blockIdx.x * 8 + (threadIdx.x >> 5);
    const int lane = threadIdx.x & 31;
    const float2* __restrict__ h2p = (const float2*)hin;

    float2 hi = h2p[node * 32 + lane];
    float rni = rn_in[node];

    // self loop: logit = ||h_i||^2 * rn_i^2  (==1 unless near-zero row)
    float part = fmaf(hi.x, hi.x, hi.y * hi.y);
    #pragma unroll
    for (int off = 16; off; off >>= 1) part += __shfl_xor_sync(0xffffffffu, part, off);
    float w = __expf(part * rni * rni);
    float s  = w;
    float ax = w * hi.x;
    float ay = w * hi.y;

    int e   = g_rowptr[node];
    int end = g_rowptr[node + 1];
    for (; e + 1 < end; e += 2) {
        int s0 = g_csr[e], s1 = g_csr[e + 1];
        float2 a0 = h2p[s0 * 32 + lane];
        float2 a1 = h2p[s1 * 32 + lane];
        float r0 = rn_in[s0], r1 = rn_in[s1];
        float d0 = fmaf(hi.x, a0.x, hi.y * a0.y);
        float d1 = fmaf(hi.x, a1.x, hi.y * a1.y);
        #pragma unroll
        for (int off = 16; off; off >>= 1) {
            d0 += __shfl_xor_sync(0xffffffffu, d0, off);
            d1 += __shfl_xor_sync(0xffffffffu, d1, off);
        }
        float w0 = __expf(d0 * rni * r0);
        float w1 = __expf(d1 * rni * r1);
        s += w0 + w1;
        ax = fmaf(w0, a0.x, fmaf(w1, a1.x, ax));
        ay = fmaf(w0, a0.y, fmaf(w1, a1.y, ay));
    }
    if (e < end) {
        int s0 = g_csr[e];
        float2 a0 = h2p[s0 * 32 + lane];
        float r0 = rn_in[s0];
        float d0 = fmaf(hi.x, a0.x, hi.y * a0.y);
        #pragma unroll
        for (int off = 16; off; off >>= 1) d0 += __shfl_xor_sync(0xffffffffu, d0, off);
        float w0 = __expf(d0 * rni * r0);
        s += w0;
        ax = fmaf(w0, a0.x, ax);
        ay = fmaf(w0, a0.y, ay);
    }

    float inv = 1.0f / s;
    float ox = ax * inv, oy = ay * inv;
    ((float2*)hout)[node * 32 + lane] = make_float2(ox, oy);

    float p2 = fmaf(ox, ox, oy * oy);
    #pragma unroll
    for (int off = 16; off; off >>= 1) p2 += __shfl_xor_sync(0xffffffffu, p2, off);
    if (lane == 0) rn_out[node] = 1.0f / fmaxf(sqrtf(p2), 1e-12f);
}

// ---------------- GEMM2 + log_softmax: warp per row ----------------
__global__ __launch_bounds__(256) void gemm2_lsm_kernel(const float* __restrict__ h,
                                                        const float* __restrict__ W2,
                                                        const float* __restrict__ b2,
                                                        float* __restrict__ out) {
    __shared__ float Ws[HD * NC];   // 10 KB
    __shared__ float bs[NC];
    const int tid = threadIdx.x;
    for (int i = tid; i < HD * NC; i += 256) Ws[i] = W2[i];
    if (tid < NC) bs[tid] = b2[tid];
    __syncthreads();

    const int lane = tid & 31;
    const int row  = blockIdx.x * 8 + (tid >> 5);

    float v0 = h[row * HD + lane];
    float v1 = h[row * HD + 32 + lane];

    float a = bs[lane];                         // col = lane     (0..31)
    float b = (lane < 8) ? bs[32 + lane] : 0.f; // col = 32+lane  (32..39)
    #pragma unroll
    for (int k = 0; k < HD; k++) {
        float xv = __shfl_sync(0xffffffffu, (k < 32) ? v0 : v1, k & 31);
        a = fmaf(xv, Ws[k * NC + lane], a);
        if (lane < 8) b = fmaf(xv, Ws[k * NC + 32 + lane], b);
    }

    float m = a;
    if (lane < 8) m = fmaxf(m, b);
    #pragma unroll
    for (int off = 16; off; off >>= 1) m = fmaxf(m, __shfl_xor_sync(0xffffffffu, m, off));

    float ssum = __expf(a - m) + ((lane < 8) ? __expf(b - m) : 0.f);
    #pragma unroll
    for (int off = 16; off; off >>= 1) ssum += __shfl_xor_sync(0xffffffffu, ssum, off);

    float lz = m + __logf(ssum);
    out[row * NC + lane] = a - lz;
    if (lane < 8) out[row * NC + 32 + lane] = b - lz;
}

// ---------------- launch ----------------
extern "C" void kernel_launch(void* const* d_in, const int* in_sizes, int n_in,
                              void* d_out, int out_size) {
    const float* x  = (const float*)d_in[0];
    const float* W1 = (const float*)d_in[1];
    const float* b1 = (const float*)d_in[2];
    const float* W2 = (const float*)d_in[3];
    const float* b2 = (const float*)d_in[4];
    const int*   ei = (const int*)d_in[5];
    const int* src = ei;
    const int* dst = ei + NE;
    float* out = (float*)d_out;

    // resolve device symbols once per call (host API, capture-safe)
    float *h_p, *h2_p, *rn_p, *rn2_p;
    cudaGetSymbolAddress((void**)&h_p,   g_h);
    cudaGetSymbolAddress((void**)&h2_p,  g_h2);
    cudaGetSymbolAddress((void**)&rn_p,  g_rn);
    cudaGetSymbolAddress((void**)&rn2_p, g_rn2);

    const int egrid = (NE + 255) / 256;

    // CSR build (per call; edges identical each call so result is stable)
    clear_deg_kernel<<<(NN + 255) / 256, 256>>>();
    hist_kernel<<<egrid, 256>>>(dst);
    scan_kernel<<<1, 1024>>>();
    scatter_kernel<<<egrid, 256>>>(src, dst);

    // lin1 + relu (+ norms)
    gemm1_kernel<<<NN / 32, 256>>>(x, W1, b1);

    // 4 AGNN layers, ping-pong
    agnn_kernel<<<NN / 8, 256>>>(h_p,  h2_p, rn_p,  rn2_p);
    agnn_kernel<<<NN / 8, 256>>>(h2_p, h_p,  rn2_p, rn_p);
    agnn_kernel<<<NN / 8, 256>>>(h_p,  h2_p, rn_p,  rn2_p);
    agnn_kernel<<<NN / 8, 256>>>(h2_p, h_p,  rn2_p, rn_p);

    // lin2 + log_softmax
    gemm2_lsm_kernel<<<NN / 8, 256>>>(h_p, W2, b2, out);

    (void)in_sizes; (void)n_in; (void)out_size;
}

// round 8
// speedup vs baseline: 1.5329x; 1.5329x over previous
#include <cuda_runtime.h>
#include <math.h>

#define NN 100000
#define NE 1600000
#define FIN 128
#define HD 64
#define NC 40
#define SCAN_BLK 98   // ceil(NN/1024)

// ---------------- scratch (static device memory: allowed) ----------------
__device__ float g_h [NN * HD];
__device__ float g_h2[NN * HD];
__device__ float g_rn [NN];
__device__ float g_rn2[NN];
__device__ int   g_deg[NN];
__device__ int   g_cursor[NN];
__device__ int   g_rowptr[NN + 1];
__device__ int   g_csr[NE];
__device__ int   g_bsum[SCAN_BLK];

// ---------------- CSR build ----------------
__global__ void clear_deg_kernel() {
    int i = blockIdx.x * blockDim.x + threadIdx.x;
    if (i < NN) g_deg[i] = 0;
}

__global__ void hist_kernel(const int* __restrict__ dst) {
    int t = blockIdx.x * blockDim.x + threadIdx.x;
    if (t < NE / 4) {
        int4 d = ((const int4*)dst)[t];
        atomicAdd(&g_deg[d.x], 1);
        atomicAdd(&g_deg[d.y], 1);
        atomicAdd(&g_deg[d.z], 1);
        atomicAdd(&g_deg[d.w], 1);
    }
}

// hierarchical exclusive scan: local (per-1024 block) -> block sums -> add
__global__ __launch_bounds__(256) void scan_local_kernel() {
    __shared__ int wsum[8];
    const int tid  = threadIdx.x;
    const int lane = tid & 31;
    const int wid  = tid >> 5;
    const int base = blockIdx.x * 1024 + tid * 4;

    int v0 = 0, v1 = 0, v2 = 0, v3 = 0;
    if (base + 3 < NN) {
        int4 d = *(const int4*)&g_deg[base];
        v0 = d.x; v1 = d.y; v2 = d.z; v3 = d.w;
    } else {
        if (base + 0 < NN) v0 = g_deg[base + 0];
        if (base + 1 < NN) v1 = g_deg[base + 1];
        if (base + 2 < NN) v2 = g_deg[base + 2];
        if (base + 3 < NN) v3 = g_deg[base + 3];
    }
    int t = v0 + v1 + v2 + v3;

    int incl = t;
    #pragma unroll
    for (int off = 1; off < 32; off <<= 1) {
        int u = __shfl_up_sync(0xffffffffu, incl, off);
        if (lane >= off) incl += u;
    }
    if (lane == 31) wsum[wid] = incl;
    __syncthreads();
    if (tid == 0) {
        int run = 0;
        #pragma unroll
        for (int i = 0; i < 8; i++) { int x = wsum[i]; wsum[i] = run; run += x; }
        g_bsum[blockIdx.x] = run;
    }
    __syncthreads();

    int excl = wsum[wid] + incl - t;   // exclusive prefix for this thread (intra-block)
    if (base + 0 < NN) g_rowptr[base + 0] = excl;
    if (base + 1 < NN) g_rowptr[base + 1] = excl + v0;
    if (base + 2 < NN) g_rowptr[base + 2] = excl + v0 + v1;
    if (base + 3 < NN) g_rowptr[base + 3] = excl + v0 + v1 + v2;
}

__global__ void scan_bsums_kernel() {   // 1 block, 128 threads
    __shared__ int sh[128];
    int tid = threadIdx.x;
    int v = (tid < SCAN_BLK) ? g_bsum[tid] : 0;
    sh[tid] = v;
    __syncthreads();
    #pragma unroll
    for (int off = 1; off < 128; off <<= 1) {
        int u = (tid >= off) ? sh[tid - off] : 0;
        __syncthreads();
        sh[tid] += u;
        __syncthreads();
    }
    if (tid < SCAN_BLK) g_bsum[tid] = sh[tid] - v;   // exclusive
}

__global__ __launch_bounds__(256) void scan_add_kernel() {
    const int base = blockIdx.x * 1024 + threadIdx.x * 4;
    const int off = g_bsum[blockIdx.x];
    #pragma unroll
    for (int i = 0; i < 4; i++) {
        int idx = base + i;
        if (idx < NN) {
            int r = g_rowptr[idx] + off;
            g_rowptr[idx] = r;
            g_cursor[idx] = r;
        }
    }
    if (blockIdx.x == 0 && threadIdx.x == 0) g_rowptr[NN] = NE;
}

__global__ void scatter_kernel(const int* __restrict__ src, const int* __restrict__ dst) {
    int t = blockIdx.x * blockDim.x + threadIdx.x;
    if (t < NE / 4) {
        int4 s = ((const int4*)src)[t];
        int4 d = ((const int4*)dst)[t];
        g_csr[atomicAdd(&g_cursor[d.x], 1)] = s.x;
        g_csr[atomicAdd(&g_cursor[d.y], 1)] = s.y;
        g_csr[atomicAdd(&g_cursor[d.z], 1)] = s.z;
        g_csr[atomicAdd(&g_cursor[d.w], 1)] = s.w;
    }
}

// ---------------- GEMM1: h = relu(x @ W1 + b1), plus inv-norms ----------------
// 256 threads / 128 rows per block. Thread (rq=tid>>3, cg=tid&7) computes
// rows rq*4..rq*4+3, cols cg*8..cg*8+7 (4x8 register tile). K in 4 phases of 32.
__global__ __launch_bounds__(256) void gemm1_kernel(const float* __restrict__ x,
                                                    const float* __restrict__ W1,
                                                    const float* __restrict__ b1) {
    __shared__ __align__(16) float Ws[32 * HD];    // 8 KB (one K-phase of W1)
    __shared__ float xs[128 * 33];                 // 16.9 KB padded
    __shared__ float bs[HD];

    const int tid = threadIdx.x;
    if (tid < HD) bs[tid] = b1[tid];

    const int row0 = blockIdx.x * 128;
    const int rq = tid >> 3;
    const int cg = tid & 7;

    float acc[4][8];
    #pragma unroll
    for (int i = 0; i < 4; i++)
        #pragma unroll
        for (int j = 0; j < 8; j++) acc[i][j] = 0.f;

    for (int ph = 0; ph < 4; ph++) {
        __syncthreads();
        #pragma unroll
        for (int i = tid; i < 32 * HD; i += 256) Ws[i] = W1[ph * 32 * HD + i];
        #pragma unroll
        for (int i = tid; i < 128 * 32; i += 256) {
            int rr = i >> 5, cc = i & 31;
            int row = row0 + rr;
            xs[rr * 33 + cc] = (row < NN) ? x[row * FIN + ph * 32 + cc] : 0.f;
        }
        __syncthreads();
        #pragma unroll 4
        for (int k = 0; k < 32; k++) {
            const float4* wp = (const float4*)&Ws[k * HD + cg * 8];
            float4 w0 = wp[0], w1 = wp[1];
            #pragma unroll
            for (int i = 0; i < 4; i++) {
                float xv = xs[(rq * 4 + i) * 33 + k];
                acc[i][0] = fmaf(xv, w0.x, acc[i][0]);
                acc[i][1] = fmaf(xv, w0.y, acc[i][1]);
                acc[i][2] = fmaf(xv, w0.z, acc[i][2]);
                acc[i][3] = fmaf(xv, w0.w, acc[i][3]);
                acc[i][4] = fmaf(xv, w1.x, acc[i][4]);
                acc[i][5] = fmaf(xv, w1.y, acc[i][5]);
                acc[i][6] = fmaf(xv, w1.z, acc[i][6]);
                acc[i][7] = fmaf(xv, w1.w, acc[i][7]);
            }
        }
    }

    #pragma unroll
    for (int i = 0; i < 4; i++) {
        float nrm = 0.f;
        #pragma unroll
        for (int j = 0; j < 8; j++) {
            float v = acc[i][j] + bs[cg * 8 + j];
            v = fmaxf(v, 0.f);
            acc[i][j] = v;
            nrm = fmaf(v, v, nrm);
        }
        // reduce across the 8 consecutive lanes (cg group) of this rq
        #pragma unroll
        for (int off = 1; off < 8; off <<= 1)
            nrm += __shfl_xor_sync(0xffffffffu, nrm, off);

        int row = row0 + rq * 4 + i;
        if (row < NN) {
            float4* out = (float4*)&g_h[row * HD + cg * 8];
            out[0] = make_float4(acc[i][0], acc[i][1], acc[i][2], acc[i][3]);
            out[1] = make_float4(acc[i][4], acc[i][5], acc[i][6], acc[i][7]);
            if (cg == 0) g_rn[row] = 1.0f / fmaxf(sqrtf(nrm), 1e-12f);
        }
    }
}

// ---------------- AGNN layer: warp per node, 16 lanes per edge ----------------
// Lanes split into two halves; each half processes one edge per step (float4/lane,
// 16 lanes cover the 64-dim row). 4-level shuffle reduction for dots. Softmax
// max-subtraction removed (logits are cosines in [-1,1]: shift-invariant & safe).
__global__ __launch_bounds__(256) void agnn_kernel(const float* __restrict__ hin,
                                                   float* __restrict__ hout,
                                                   const float* __restrict__ rn_in,
                                                   float* __restrict__ rn_out) {
    const int node = blockIdx.x * 8 + (threadIdx.x >> 5);
    const int lane = threadIdx.x & 31;
    const int half = lane >> 4;
    const int q    = lane & 15;
    const float4* __restrict__ h4 = (const float4*)hin;

    const float4 hi = h4[node * 16 + q];
    const float rni = __ldg(&rn_in[node]);

    // self loop (count once: half 0 only)
    float d = fmaf(hi.x, hi.x, fmaf(hi.y, hi.y, fmaf(hi.z, hi.z, hi.w * hi.w)));
    #pragma unroll
    for (int off = 1; off < 16; off <<= 1) d += __shfl_xor_sync(0xffffffffu, d, off);
    float w = (half == 0) ? __expf(d * rni * rni) : 0.f;
    float s = w;
    float4 acc = make_float4(w * hi.x, w * hi.y, w * hi.z, w * hi.w);

    int e = g_rowptr[node];
    const int end = g_rowptr[node + 1];

    // prefetch indices one iteration ahead
    int nA = 0, nB = 0;
    if (e + 4 <= end) { nA = g_csr[e + half]; nB = g_csr[e + 2 + half]; }

    for (; e + 4 <= end; e += 4) {
        const int sA = nA, sB = nB;
        if (e + 8 <= end) { nA = g_csr[e + 4 + half]; nB = g_csr[e + 6 + half]; }
        float4 aA = h4[sA * 16 + q];
        float4 aB = h4[sB * 16 + q];
        float rA = __ldg(&rn_in[sA]);
        float rB = __ldg(&rn_in[sB]);
        float dA = fmaf(hi.x, aA.x, fmaf(hi.y, aA.y, fmaf(hi.z, aA.z, hi.w * aA.w)));
        float dB = fmaf(hi.x, aB.x, fmaf(hi.y, aB.y, fmaf(hi.z, aB.z, hi.w * aB.w)));
        #pragma unroll
        for (int off = 1; off < 16; off <<= 1) {
            dA += __shfl_xor_sync(0xffffffffu, dA, off);
            dB += __shfl_xor_sync(0xffffffffu, dB, off);
        }
        float wA = __expf(dA * rni * rA);
        float wB = __expf(dB * rni * rB);
        s += wA + wB;
        acc.x = fmaf(wA, aA.x, fmaf(wB, aB.x, acc.x));
        acc.y = fmaf(wA, aA.y, fmaf(wB, aB.y, acc.y));
        acc.z = fmaf(wA, aA.z, fmaf(wB, aB.z, acc.z));
        acc.w = fmaf(wA, aA.w, fmaf(wB, aB.w, acc.w));
    }
    for (; e < end; e += 2) {
        const int idx = e + half;
        const bool valid = idx < end;
        const int sA = g_csr[valid ? idx : end - 1];
        float4 aA = h4[sA * 16 + q];
        float rA = __ldg(&rn_in[sA]);
        float dA = fmaf(hi.x, aA.x, fmaf(hi.y, aA.y, fmaf(hi.z, aA.z, hi.w * aA.w)));
        #pragma unroll
        for (int off = 1; off < 16; off <<= 1) dA += __shfl_xor_sync(0xffffffffu, dA, off);
        float wA = valid ? __expf(dA * rni * rA) : 0.f;
        s += wA;
        acc.x = fmaf(wA, aA.x, acc.x);
        acc.y = fmaf(wA, aA.y, acc.y);
        acc.z = fmaf(wA, aA.z, acc.z);
        acc.w = fmaf(wA, aA.w, acc.w);
    }

    // combine the two halves
    s     += __shfl_xor_sync(0xffffffffu, s,     16);
    acc.x += __shfl_xor_sync(0xffffffffu, acc.x, 16);
    acc.y += __shfl_xor_sync(0xffffffffu, acc.y, 16);
    acc.z += __shfl_xor_sync(0xffffffffu, acc.z, 16);
    acc.w += __shfl_xor_sync(0xffffffffu, acc.w, 16);

    const float inv = 1.0f / s;
    const float4 o = make_float4(acc.x * inv, acc.y * inv, acc.z * inv, acc.w * inv);

    float p = fmaf(o.x, o.x, fmaf(o.y, o.y, fmaf(o.z, o.z, o.w * o.w)));
    #pragma unroll
    for (int off = 1; off < 16; off <<= 1) p += __shfl_xor_sync(0xffffffffu, p, off);

    if (half == 0) {
        ((float4*)hout)[node * 16 + q] = o;
        if (q == 0) rn_out[node] = 1.0f / fmaxf(sqrtf(p), 1e-12f);
    }
}

// ---------------- GEMM2 + log_softmax: warp per row ----------------
__global__ __launch_bounds__(256) void gemm2_lsm_kernel(const float* __restrict__ h,
                                                        const float* __restrict__ W2,
                                                        const float* __restrict__ b2,
                                                        float* __restrict__ out) {
    __shared__ float Ws[HD * NC];   // 10 KB
    __shared__ float bs[NC];
    const int tid = threadIdx.x;
    for (int i = tid; i < HD * NC; i += 256) Ws[i] = W2[i];
    if (tid < NC) bs[tid] = b2[tid];
    __syncthreads();

    const int lane = tid & 31;
    const int row  = blockIdx.x * 8 + (tid >> 5);

    float v0 = h[row * HD + lane];
    float v1 = h[row * HD + 32 + lane];

    float a = bs[lane];                         // cols 0..31
    float b = (lane < 8) ? bs[32 + lane] : 0.f; // cols 32..39
    #pragma unroll
    for (int k = 0; k < 32; k++) {
        float xv = __shfl_sync(0xffffffffu, v0, k);
        a = fmaf(xv, Ws[k * NC + lane], a);
        if (lane < 8) b = fmaf(xv, Ws[k * NC + 32 + lane], b);
    }
    #pragma unroll
    for (int k = 0; k < 32; k++) {
        float xv = __shfl_sync(0xffffffffu, v1, k);
        a = fmaf(xv, Ws[(32 + k) * NC + lane], a);
        if (lane < 8) b = fmaf(xv, Ws[(32 + k) * NC + 32 + lane], b);
    }

    float m = a;
    if (lane < 8) m = fmaxf(m, b);
    #pragma unroll
    for (int off = 16; off; off >>= 1) m = fmaxf(m, __shfl_xor_sync(0xffffffffu, m, off));

    float ssum = __expf(a - m) + ((lane < 8) ? __expf(b - m) : 0.f);
    #pragma unroll
    for (int off = 16; off; off >>= 1) ssum += __shfl_xor_sync(0xffffffffu, ssum, off);

    float lz = m + __logf(ssum);
    out[row * NC + lane] = a - lz;
    if (lane < 8) out[row * NC + 32 + lane] = b - lz;
}

// ---------------- launch ----------------
extern "C" void kernel_launch(void* const* d_in, const int* in_sizes, int n_in,
                              void* d_out, int out_size) {
    const float* x  = (const float*)d_in[0];
    const float* W1 = (const float*)d_in[1];
    const float* b1 = (const float*)d_in[2];
    const float* W2 = (const float*)d_in[3];
    const float* b2 = (const float*)d_in[4];
    const int*   ei = (const int*)d_in[5];
    const int* src = ei;
    const int* dst = ei + NE;
    float* out = (float*)d_out;

    float *h_p, *h2_p, *rn_p, *rn2_p;
    cudaGetSymbolAddress((void**)&h_p,   g_h);
    cudaGetSymbolAddress((void**)&h2_p,  g_h2);
    cudaGetSymbolAddress((void**)&rn_p,  g_rn);
    cudaGetSymbolAddress((void**)&rn2_p, g_rn2);

    const int e4grid = (NE / 4 + 255) / 256;

    // CSR build
    clear_deg_kernel<<<(NN + 255) / 256, 256>>>();
    hist_kernel<<<e4grid, 256>>>(dst);
    scan_local_kernel<<<SCAN_BLK, 256>>>();
    scan_bsums_kernel<<<1, 128>>>();
    scan_add_kernel<<<SCAN_BLK, 256>>>();
    scatter_kernel<<<e4grid, 256>>>(src, dst);

    // lin1 + relu (+ norms)
    gemm1_kernel<<<(NN + 127) / 128, 256>>>(x, W1, b1);

    // 4 AGNN layers, ping-pong
    agnn_kernel<<<NN / 8, 256>>>(h_p,  h2_p, rn_p,  rn2_p);
    agnn_kernel<<<NN / 8, 256>>>(h2_p, h_p,  rn2_p, rn_p);
    agnn_kernel<<<NN / 8, 256>>>(h_p,  h2_p, rn_p,  rn2_p);
    agnn_kernel<<<NN / 8, 256>>>(h2_p, h_p,  rn2_p, rn_p);

    // lin2 + log_softmax
    gemm2_lsm_kernel<<<NN / 8, 256>>>(h_p, W2, b2, out);

    (void)in_sizes; (void)n_in; (void)out_size;
}